// round 13
// baseline (speedup 1.0000x reference)
#include <cuda_runtime.h>
#include <cuda_fp16.h>
#include <cstdint>
#include <cstddef>

#define NE 8192
#define NF 64
#define NH 256
#define NN (128*8192)
#define NGT 32768            // 32-row group-tiles
#define NTHREADS 512

// smem byte offsets
#define OFF_SA   0u          // 4 x [32 rows][128k] f16, 8KB per group
#define OFF_SH   32768u      // 4 x [32 rows][256k] f16, 16KB per group
#define OFF_SW1  98304u      // W1^T [256n][128k] f16
#define OFF_SW2  163840u     // W2^T [128n][256k] f16
#define OFF_SB1  229376u     // (unused, kept for layout stability)
#define OFF_SB2  230400u
#define OFF_FLG  230912u     // 4 x u32 mismatch flags
#define SMEM_REQ 231040

__device__ __forceinline__ uint32_t smem_u32(const void* p){
    uint32_t a;
    asm("{ .reg .u64 t; cvta.to.shared.u64 t, %1; cvt.u32.u64 %0, t; }" : "=r"(a) : "l"(p));
    return a;
}
__device__ __forceinline__ uint32_t pack_h2(float a, float b){
    __half2 h = __floats2half2_rn(a, b);
    return *reinterpret_cast<uint32_t*>(&h);
}
__device__ __forceinline__ void ldmx4(uint32_t& a0, uint32_t& a1, uint32_t& a2, uint32_t& a3, uint32_t addr){
    asm volatile("ldmatrix.sync.aligned.m8n8.x4.shared.b16 {%0,%1,%2,%3}, [%4];"
                 : "=r"(a0), "=r"(a1), "=r"(a2), "=r"(a3) : "r"(addr));
}
__device__ __forceinline__ uint32_t lds32(uint32_t addr){
    uint32_t v; asm volatile("ld.shared.b32 %0, [%1];" : "=r"(v) : "r"(addr)); return v;
}
__device__ __forceinline__ void sts32(uint32_t addr, uint32_t v){
    asm volatile("st.shared.b32 [%0], %1;" :: "r"(addr), "r"(v) : "memory");
}
__device__ __forceinline__ void sts64(uint32_t addr, uint32_t v0, uint32_t v1){
    asm volatile("st.shared.v2.b32 [%0], {%1,%2};" :: "r"(addr), "r"(v0), "r"(v1) : "memory");
}
__device__ __forceinline__ void sts128(uint32_t addr, uint32_t p0, uint32_t p1, uint32_t p2, uint32_t p3){
    asm volatile("st.shared.v4.b32 [%0], {%1,%2,%3,%4};" :: "r"(addr), "r"(p0), "r"(p1), "r"(p2), "r"(p3) : "memory");
}
__device__ __forceinline__ void mma16(float c[4], uint32_t a0, uint32_t a1, uint32_t a2, uint32_t a3,
                                      uint32_t b0, uint32_t b1){
    asm volatile(
        "mma.sync.aligned.m16n8k16.row.col.f32.f16.f16.f32 "
        "{%0,%1,%2,%3},{%4,%5,%6,%7},{%8,%9},{%0,%1,%2,%3};\n"
        : "+f"(c[0]), "+f"(c[1]), "+f"(c[2]), "+f"(c[3])
        : "r"(a0), "r"(a1), "r"(a2), "r"(a3), "r"(b0), "r"(b1));
}
// h = max(pack_f16(a,b) + bias_h2, 0) — packed f16 epilogue
__device__ __forceinline__ uint32_t relu_bias_h2(float a, float b, uint32_t bias){
    __half2 v = __floats2half2_rn(a, b);
    __half2 bb = *reinterpret_cast<__half2*>(&bias);
    v = __hmax2(__hadd2(v, bb), __float2half2_rn(0.f));
    return *reinterpret_cast<uint32_t*>(&v);
}

__global__ void __launch_bounds__(NTHREADS, 1)
fused_h16k(const float* __restrict__ x,  const float* __restrict__ gf,
           const float* __restrict__ W1, const float* __restrict__ b1g,
           const float* __restrict__ W2, const float* __restrict__ b2g,
           const int*   __restrict__ pidx, float* __restrict__ out, int write_event)
{
    extern __shared__ char sm[];
    const int tid  = threadIdx.x;
    const int warp = tid >> 5, lane = tid & 31;
    const int grp = lane >> 2, tig = lane & 3;
    const int wg = warp >> 2, wn = warp & 3;   // 4 groups x 4 n-warps
    const int tid_g = tid & 127;

    const uint32_t smu  = smem_u32(sm);
    const uint32_t sA_g = smu + OFF_SA + (uint32_t)wg * 8192u;
    const uint32_t sH_g = smu + OFF_SH + (uint32_t)wg * 16384u;
    const uint32_t flagA = smu + OFF_FLG + (uint32_t)wg * 4u;
    float* sb2 = (float*)(sm + OFF_SB2);

    // ---- one-time weight preload (swizzled f16) ----
    for (int i = tid; i < 128 * NH; i += NTHREADS) {
        int k = i >> 8, n = i & 255;
        uint32_t cb = (uint32_t)(2 * k);
        uint32_t off = (uint32_t)n * 256u + ((cb & ~15u) ^ (((uint32_t)n & 7u) << 4)) + (cb & 15u);
        *(half*)(sm + OFF_SW1 + off) = __float2half_rn(W1[i]);
    }
    for (int i = tid; i < NH * 128; i += NTHREADS) {
        int k = i >> 7, n = i & 127;
        uint32_t cb = (uint32_t)(2 * k);
        uint32_t off = (uint32_t)n * 512u + ((cb & ~15u) ^ (((uint32_t)n & 7u) << 4)) + (cb & 15u);
        *(half*)(sm + OFF_SW2 + off) = __float2half_rn(W2[i]);
    }
    if (tid < 128) sb2[tid] = b2g[tid];
    if (tid_g == 0) sts32(flagA, 0u);
    __syncthreads();   // last CTA-wide sync

    // per-thread constants
    const uint32_t amask = ((uint32_t)(lane & 7)) << 4;   // A ldmatrix swizzle
    const uint32_t ahi   = ((uint32_t)(lane >> 4)) << 4;  // A k-half select
    const int lr = lane & 15;

    // B ldmatrix lane mapping
    const uint32_t browSel = (uint32_t)(((lane & 16) >> 1) + (lane & 7));
    const uint32_t bq      = (uint32_t)((lane & 8) << 1);
    const uint32_t bmsk    = ((uint32_t)(lane & 7)) << 4;

    const int nb1 = wn * 64;
    const int nb2 = wn * 32;
    const uint32_t b1Ldsm = smu + OFF_SW1 + ((uint32_t)nb1 + browSel) * 256u;
    const uint32_t b2Ldsm = smu + OFF_SW2 + ((uint32_t)nb2 + browSel) * 512u;

    uint32_t a1Base[2], a2Base[2];
    #pragma unroll
    for (int mf = 0; mf < 2; mf++) {
        a1Base[mf] = sA_g + (uint32_t)(16*mf + lr) * 256u;
        a2Base[mf] = sH_g + (uint32_t)(16*mf + lr) * 512u;
    }

    // cached packed b1 bias: 8 x f16x2, tile-invariant per thread
    uint32_t bh2[8];
    #pragma unroll
    for (int nt = 0; nt < 8; nt++) {
        const int c0 = nb1 + nt*8 + 2*tig;
        bh2[nt] = pack_h2(b1g[c0], b1g[c0+1]);
    }

    // phase-A assignments
    const int gr2 = tid_g >> 2, gq2 = tid_g & 3;

    const int G0    = (blockIdx.x << 2) + wg;
    const int gstep = gridDim.x << 2;
    int pi_cur = pidx[G0 * 32 + gr2];

    #define BARG() asm volatile("bar.sync %0, 128;" :: "r"(wg + 4) : "memory")

    // ================= persistent group-tile loop =================
    for (int mb = G0; mb < NGT; mb += gstep) {
        const int row_g = mb * 32 + gr2;

        // ---- Phase A: merged gather + identity copy + event ----
        {
            if (pi_cur != row_g) sts32(flagA, 1u);

            const float4* gs = (const float4*)(gf + (size_t)(((unsigned)pi_cur) & (NE-1)) * NF) + gq2 * 4;
            float4 g0 = gs[0], g1 = gs[1], g2 = gs[2], g3 = gs[3];

            const uint4* xs = (const uint4*)x + (size_t)mb * 512;
            uint4 c0 = xs[tid_g], c1 = xs[tid_g + 128], c2 = xs[tid_g + 256], c3 = xs[tid_g + 384];

            uint4* od = (uint4*)out + (size_t)mb * 512;
            od[tid_g] = c0; od[tid_g + 128] = c1; od[tid_g + 256] = c2; od[tid_g + 384] = c3;

            // gf STS: f16 bytes [128 + gq2*32, +32) of row gr2
            {
                const uint32_t rb  = sA_g + (uint32_t)gr2 * 256u;
                const uint32_t msk = ((uint32_t)(gr2 & 7)) << 4;
                sts128(rb + ((128u + (uint32_t)gq2 * 32u) ^ msk),
                       pack_h2(g0.x, g0.y), pack_h2(g0.z, g0.w),
                       pack_h2(g1.x, g1.y), pack_h2(g1.z, g1.w));
                sts128(rb + ((128u + (uint32_t)gq2 * 32u + 16u) ^ msk),
                       pack_h2(g2.x, g2.y), pack_h2(g2.z, g2.w),
                       pack_h2(g3.x, g3.y), pack_h2(g3.z, g3.w));
            }
            // x part STS from copy regs (fast path: x[row] == x[pidx[row]])
            {
                const uint32_t colu = (uint32_t)((tid_g & 15) >> 1) * 16u;
                const uint32_t sub  = (uint32_t)(tid_g & 1) * 8u;
                const int rbase = tid_g >> 4;
                uint4 cc[4] = {c0, c1, c2, c3};
                #pragma unroll
                for (int j = 0; j < 4; j++) {
                    const int rj = rbase + 8 * j;
                    const float4 f = *(float4*)&cc[j];
                    const uint32_t addr = sA_g + (uint32_t)rj * 256u
                                        + (colu ^ (((uint32_t)(rj & 7)) << 4)) + sub;
                    sts64(addr, pack_h2(f.x, f.y), pack_h2(f.z, f.w));
                }
            }
            if (write_event && tid_g < 96) {
                int ei = mb * 96 + tid_g;
                out[(size_t)3 * NN * NF + ei] = (float)(ei & (NE - 1));
            }
        }
        BARG();   // sA_g ready (fast path)

        // ---- repair path (group-uniform; never taken for arange pidx) ----
        if (lds32(flagA) != 0u) {
            const float4* xsrc = (const float4*)(x + (size_t)pi_cur * NF) + gq2 * 4;
            float4 h0 = xsrc[0], h1 = xsrc[1], h2 = xsrc[2], h3 = xsrc[3];
            const uint32_t rb  = sA_g + (uint32_t)gr2 * 256u;
            const uint32_t msk = ((uint32_t)(gr2 & 7)) << 4;
            sts128(rb + (((uint32_t)gq2 * 32u) ^ msk),
                   pack_h2(h0.x, h0.y), pack_h2(h0.z, h0.w),
                   pack_h2(h1.x, h1.y), pack_h2(h1.z, h1.w));
            sts128(rb + (((uint32_t)gq2 * 32u + 16u) ^ msk),
                   pack_h2(h2.x, h2.y), pack_h2(h2.z, h2.w),
                   pack_h2(h3.x, h3.y), pack_h2(h3.z, h3.w));
            if (tid_g == 0) sts32(flagA, 0u);
            BARG();
        }

        // prefetch next tile's pidx
        {
            int mn = mb + gstep;
            if (mn < NGT) pi_cur = pidx[mn * 32 + gr2];
        }

        // ---- GEMM1: C1(32x256) = A(32x128) @ W1 ----
        float acc1[2][8][4];
        #pragma unroll
        for (int mf=0; mf<2; mf++)
            #pragma unroll
            for (int nt=0; nt<8; nt++)
                #pragma unroll
                for (int i=0;i<4;i++) acc1[mf][nt][i]=0.f;

        #pragma unroll
        for (int kk = 0; kk < 8; kk++) {
            const uint32_t ksw  = (((uint32_t)(kk*32)) + ahi) ^ amask;
            const uint32_t koff = (((uint32_t)(kk*32)) + bq)  ^ bmsk;
            uint32_t A[2][4];
            #pragma unroll
            for (int mf = 0; mf < 2; mf++)
                ldmx4(A[mf][0],A[mf][1],A[mf][2],A[mf][3], a1Base[mf] + ksw);
            #pragma unroll
            for (int j = 0; j < 4; j++) {
                uint32_t b0,b1,b2,b3;
                ldmx4(b0,b1,b2,b3, b1Ldsm + (uint32_t)j*4096u + koff);
                #pragma unroll
                for (int mf = 0; mf < 2; mf++) {
                    mma16(acc1[mf][2*j],   A[mf][0],A[mf][1],A[mf][2],A[mf][3], b0, b1);
                    mma16(acc1[mf][2*j+1], A[mf][0],A[mf][1],A[mf][2],A[mf][3], b2, b3);
                }
            }
        }

        // ---- Epilogue 1: packed f16 bias+relu -> sH_g, keep own slice in regs ----
        uint32_t hA[2][8], hB[2][8];
        #pragma unroll
        for (int mf=0; mf<2; mf++){
            const uint32_t rb0 = sH_g + (uint32_t)(16*mf + grp) * 512u;
            const uint32_t rb1 = rb0 + 8u * 512u;
            #pragma unroll
            for (int nt=0; nt<8; nt++){
                uint32_t p01 = relu_bias_h2(acc1[mf][nt][0], acc1[mf][nt][1], bh2[nt]);
                uint32_t p23 = relu_bias_h2(acc1[mf][nt][2], acc1[mf][nt][3], bh2[nt]);
                const uint32_t csw = (((uint32_t)(128*wn + nt*16)) ^ (((uint32_t)grp) << 4)) + (uint32_t)(4*tig);
                sts32(rb0 + csw, p01);
                sts32(rb1 + csw, p23);
                hA[mf][nt] = p01; hB[mf][nt] = p23;
            }
        }

        // ---- GEMM2 diagonal k-steps (own h slice, register-direct; pre-barrier) ----
        float acc2[2][4][4];
        #pragma unroll
        for (int mf=0; mf<2; mf++)
            #pragma unroll
            for (int nt=0; nt<4; nt++)
                #pragma unroll
                for (int i=0;i<4;i++) acc2[mf][nt][i]=0.f;

        #pragma unroll
        for (int kkl = 0; kkl < 4; kkl++) {
            const int s = wn * 4 + kkl;
            uint32_t A[2][4];
            #pragma unroll
            for (int mf = 0; mf < 2; mf++) {
                A[mf][0] = hA[mf][2*kkl];   A[mf][1] = hB[mf][2*kkl];
                A[mf][2] = hA[mf][2*kkl+1]; A[mf][3] = hB[mf][2*kkl+1];
            }
            const uint32_t koff = (((uint32_t)(s*32)) + bq) ^ bmsk;
            #pragma unroll
            for (int j = 0; j < 2; j++) {
                uint32_t b0,b1,b2,b3;
                ldmx4(b0,b1,b2,b3, b2Ldsm + (uint32_t)j*8192u + koff);
                #pragma unroll
                for (int mf = 0; mf < 2; mf++) {
                    mma16(acc2[mf][2*j],   A[mf][0],A[mf][1],A[mf][2],A[mf][3], b0, b1);
                    mma16(acc2[mf][2*j+1], A[mf][0],A[mf][1],A[mf][2],A[mf][3], b2, b3);
                }
            }
        }
        BARG();   // sH_g ready; all warps past GEMM1 (sA_g reusable next iter)

        // ---- GEMM2 off-diagonal k-steps (other warps' h via smem) ----
        #pragma unroll
        for (int s = 0; s < 16; s++) {
            if ((s >> 2) == wn) continue;   // diagonal already done
            const uint32_t ksw = (((uint32_t)(s*32)) + ahi) ^ amask;
            uint32_t A[2][4];
            #pragma unroll
            for (int mf = 0; mf < 2; mf++)
                ldmx4(A[mf][0],A[mf][1],A[mf][2],A[mf][3], a2Base[mf] + ksw);
            const uint32_t koff = (((uint32_t)(s*32)) + bq) ^ bmsk;
            #pragma unroll
            for (int j = 0; j < 2; j++) {
                uint32_t b0,b1,b2,b3;
                ldmx4(b0,b1,b2,b3, b2Ldsm + (uint32_t)j*8192u + koff);
                #pragma unroll
                for (int mf = 0; mf < 2; mf++) {
                    mma16(acc2[mf][2*j],   A[mf][0],A[mf][1],A[mf][2],A[mf][3], b0, b1);
                    mma16(acc2[mf][2*j+1], A[mf][0],A[mf][1],A[mf][2],A[mf][3], b2, b3);
                }
            }
        }

        // ---- Epilogue 2: bias + branch-permuted scatter ----
        const int p  = mb >> 8;
        const int e0 = (mb << 5) & (NE - 1);
        #pragma unroll
        for (int mf=0; mf<2; mf++){
            const int r0 = 16*mf + grp;
            #pragma unroll
            for (int nt=0; nt<4; nt++){
                const int c0 = nb2 + nt*8 + 2*tig;
                const int br = c0 >> 6, fc = c0 & 63;
                const size_t rowbase = (size_t)NN + (size_t)(2*p + br) * NE + (size_t)e0;
                float bz0 = sb2[c0], bz1 = sb2[c0+1];
                float2 v0 = { acc2[mf][nt][0] + bz0, acc2[mf][nt][1] + bz1 };
                float2 v1 = { acc2[mf][nt][2] + bz0, acc2[mf][nt][3] + bz1 };
                *(float2*)(out + (rowbase + r0)     * NF + fc) = v0;
                *(float2*)(out + (rowbase + r0 + 8) * NF + fc) = v1;
            }
        }
    }
    #undef BARG
}

extern "C" void kernel_launch(void* const* d_in, const int* in_sizes, int n_in,
                              void* d_out, int out_size)
{
    const float* x   = (const float*)d_in[0];
    const float* gf  = (const float*)d_in[1];
    const float* W1  = (const float*)d_in[2];
    const float* b1  = (const float*)d_in[3];
    const float* W2  = (const float*)d_in[4];
    const float* b2  = (const float*)d_in[5];
    const int*  pidx = (const int*)d_in[6];
    float* out = (float*)d_out;

    int write_event = (out_size >= (3 * NN * NF + 3 * NN)) ? 1 : 0;

    int dev = 0, nsm = 148;
    cudaGetDevice(&dev);
    cudaDeviceGetAttribute(&nsm, cudaDevAttrMultiProcessorCount, dev);
    if (nsm <= 0 || nsm > 8192) nsm = 148;

    cudaFuncSetAttribute(fused_h16k, cudaFuncAttributeMaxDynamicSharedMemorySize, SMEM_REQ);
    fused_h16k<<<nsm, NTHREADS, SMEM_REQ>>>(x, gf, W1, b1, W2, b2, pidx, out, write_event);
}

// round 14
// speedup vs baseline: 1.5454x; 1.5454x over previous
#include <cuda_runtime.h>
#include <cuda_fp16.h>
#include <cstdint>
#include <cstddef>

#define NE 8192
#define NF 64
#define NH 256
#define NN (128*8192)
#define NGT 32768            // 32-row group-tiles
#define NTHREADS 512

// smem byte offsets
#define OFF_SA   0u          // 4 x [32 rows][128k] f16, 8KB per group
#define OFF_SH   32768u      // 4 x [32 rows][256k] f16, 16KB per group
#define OFF_SW1  98304u      // W1^T [256n][128k] f16
#define OFF_SW2  163840u     // W2^T [128n][256k] f16
#define OFF_SB2  230400u
#define OFF_FLG  230912u     // 4 x u32 mismatch flags
#define SMEM_REQ 231040

__device__ __forceinline__ uint32_t smem_u32(const void* p){
    uint32_t a;
    asm("{ .reg .u64 t; cvta.to.shared.u64 t, %1; cvt.u32.u64 %0, t; }" : "=r"(a) : "l"(p));
    return a;
}
__device__ __forceinline__ uint32_t pack_h2(float a, float b){
    __half2 h = __floats2half2_rn(a, b);
    return *reinterpret_cast<uint32_t*>(&h);
}
__device__ __forceinline__ void ldmx4(uint32_t& a0, uint32_t& a1, uint32_t& a2, uint32_t& a3, uint32_t addr){
    asm volatile("ldmatrix.sync.aligned.m8n8.x4.shared.b16 {%0,%1,%2,%3}, [%4];"
                 : "=r"(a0), "=r"(a1), "=r"(a2), "=r"(a3) : "r"(addr));
}
__device__ __forceinline__ uint32_t lds32(uint32_t addr){
    uint32_t v; asm volatile("ld.shared.b32 %0, [%1];" : "=r"(v) : "r"(addr)); return v;
}
__device__ __forceinline__ void sts32(uint32_t addr, uint32_t v){
    asm volatile("st.shared.b32 [%0], %1;" :: "r"(addr), "r"(v) : "memory");
}
__device__ __forceinline__ void sts64(uint32_t addr, uint32_t v0, uint32_t v1){
    asm volatile("st.shared.v2.b32 [%0], {%1,%2};" :: "r"(addr), "r"(v0), "r"(v1) : "memory");
}
__device__ __forceinline__ void sts128(uint32_t addr, uint32_t p0, uint32_t p1, uint32_t p2, uint32_t p3){
    asm volatile("st.shared.v4.b32 [%0], {%1,%2,%3,%4};" :: "r"(addr), "r"(p0), "r"(p1), "r"(p2), "r"(p3) : "memory");
}
__device__ __forceinline__ void mma16(float c[4], uint32_t a0, uint32_t a1, uint32_t a2, uint32_t a3,
                                      uint32_t b0, uint32_t b1){
    asm volatile(
        "mma.sync.aligned.m16n8k16.row.col.f32.f16.f16.f32 "
        "{%0,%1,%2,%3},{%4,%5,%6,%7},{%8,%9},{%0,%1,%2,%3};\n"
        : "+f"(c[0]), "+f"(c[1]), "+f"(c[2]), "+f"(c[3])
        : "r"(a0), "r"(a1), "r"(a2), "r"(a3), "r"(b0), "r"(b1));
}
// h = max(pack_f16(a,b) + bias_h2, 0) — packed f16 epilogue
__device__ __forceinline__ uint32_t relu_bias_h2(float a, float b, uint32_t bias){
    __half2 v = __floats2half2_rn(a, b);
    __half2 bb = *reinterpret_cast<__half2*>(&bias);
    v = __hmax2(__hadd2(v, bb), __float2half2_rn(0.f));
    return *reinterpret_cast<uint32_t*>(&v);
}

__global__ void __launch_bounds__(NTHREADS, 1)
fused_h16m(const float* __restrict__ x,  const float* __restrict__ gf,
           const float* __restrict__ W1, const float* __restrict__ b1g,
           const float* __restrict__ W2, const float* __restrict__ b2g,
           const int*   __restrict__ pidx, float* __restrict__ out, int write_event)
{
    extern __shared__ char sm[];
    const int tid  = threadIdx.x;
    const int warp = tid >> 5, lane = tid & 31;
    const int grp = lane >> 2, tig = lane & 3;
    const int wg = warp >> 2, wn = warp & 3;   // 4 groups x 4 n-warps
    const int tid_g = tid & 127;

    const uint32_t smu  = smem_u32(sm);
    const uint32_t sA_g = smu + OFF_SA + (uint32_t)wg * 8192u;
    const uint32_t sH_g = smu + OFF_SH + (uint32_t)wg * 16384u;
    const uint32_t flagA = smu + OFF_FLG + (uint32_t)wg * 4u;
    float* sb2 = (float*)(sm + OFF_SB2);

    // ---- one-time weight preload (swizzled f16) ----
    for (int i = tid; i < 128 * NH; i += NTHREADS) {
        int k = i >> 8, n = i & 255;
        uint32_t cb = (uint32_t)(2 * k);
        uint32_t off = (uint32_t)n * 256u + ((cb & ~15u) ^ (((uint32_t)n & 7u) << 4)) + (cb & 15u);
        *(half*)(sm + OFF_SW1 + off) = __float2half_rn(W1[i]);
    }
    for (int i = tid; i < NH * 128; i += NTHREADS) {
        int k = i >> 7, n = i & 127;
        uint32_t cb = (uint32_t)(2 * k);
        uint32_t off = (uint32_t)n * 512u + ((cb & ~15u) ^ (((uint32_t)n & 7u) << 4)) + (cb & 15u);
        *(half*)(sm + OFF_SW2 + off) = __float2half_rn(W2[i]);
    }
    if (tid < 128) sb2[tid] = b2g[tid];
    if (tid_g == 0) sts32(flagA, 0u);
    __syncthreads();   // last CTA-wide sync

    // per-thread constants
    const uint32_t amask = ((uint32_t)(lane & 7)) << 4;   // A ldmatrix swizzle
    const uint32_t ahi   = ((uint32_t)(lane >> 4)) << 4;  // A k-half select
    const int lr = lane & 15;

    // B ldmatrix lane mapping
    const uint32_t browSel = (uint32_t)(((lane & 16) >> 1) + (lane & 7));
    const uint32_t bq      = (uint32_t)((lane & 8) << 1);
    const uint32_t bmsk    = ((uint32_t)(lane & 7)) << 4;

    const int nb1 = wn * 64;
    const int nb2 = wn * 32;
    const uint32_t b1Ldsm = smu + OFF_SW1 + ((uint32_t)nb1 + browSel) * 256u;
    const uint32_t b2Ldsm = smu + OFF_SW2 + ((uint32_t)nb2 + browSel) * 512u;

    uint32_t a1Base[2], a2Base[2];
    #pragma unroll
    for (int mf = 0; mf < 2; mf++) {
        a1Base[mf] = sA_g + (uint32_t)(16*mf + lr) * 256u;
        a2Base[mf] = sH_g + (uint32_t)(16*mf + lr) * 512u;
    }

    // cached packed b1 bias: 8 x f16x2, tile-invariant per thread
    uint32_t bh2[8];
    #pragma unroll
    for (int nt = 0; nt < 8; nt++) {
        const int c0 = nb1 + nt*8 + 2*tig;
        bh2[nt] = pack_h2(b1g[c0], b1g[c0+1]);
    }

    // phase-A assignments
    const int gr2 = tid_g >> 2, gq2 = tid_g & 3;

    const int G0    = (blockIdx.x << 2) + wg;
    const int gstep = gridDim.x << 2;
    int pi_cur = pidx[G0 * 32 + gr2];

    #define BARG() asm volatile("bar.sync %0, 128;" :: "r"(wg + 4) : "memory")

    // ================= persistent group-tile loop =================
    for (int mb = G0; mb < NGT; mb += gstep) {
        const int row_g = mb * 32 + gr2;

        // ---- Phase A: merged gather + identity copy + event ----
        {
            if (pi_cur != row_g) sts32(flagA, 1u);

            // gf part: row gr2, quarter gq2 (always uses real pi)
            const float4* gs = (const float4*)(gf + (size_t)(((unsigned)pi_cur) & (NE-1)) * NF) + gq2 * 4;
            float4 g0 = gs[0], g1 = gs[1], g2 = gs[2], g3 = gs[3];

            // identity copy load (independent addresses, MLP with gf loads)
            const uint4* xs = (const uint4*)x + (size_t)mb * 512;
            uint4 c0 = xs[tid_g], c1 = xs[tid_g + 128], c2 = xs[tid_g + 256], c3 = xs[tid_g + 384];

            // copy STG (coalesced)
            uint4* od = (uint4*)out + (size_t)mb * 512;
            od[tid_g] = c0; od[tid_g + 128] = c1; od[tid_g + 256] = c2; od[tid_g + 384] = c3;

            // gf STS: f16 bytes [128 + gq2*32, +32) of row gr2
            {
                const uint32_t rb  = sA_g + (uint32_t)gr2 * 256u;
                const uint32_t msk = ((uint32_t)(gr2 & 7)) << 4;
                sts128(rb + ((128u + (uint32_t)gq2 * 32u) ^ msk),
                       pack_h2(g0.x, g0.y), pack_h2(g0.z, g0.w),
                       pack_h2(g1.x, g1.y), pack_h2(g1.z, g1.w));
                sts128(rb + ((128u + (uint32_t)gq2 * 32u + 16u) ^ msk),
                       pack_h2(g2.x, g2.y), pack_h2(g2.z, g2.w),
                       pack_h2(g3.x, g3.y), pack_h2(g3.z, g3.w));
            }
            // x part STS from copy regs (fast path: x[row] == x[pidx[row]])
            {
                const uint32_t colu = (uint32_t)((tid_g & 15) >> 1) * 16u;
                const uint32_t sub  = (uint32_t)(tid_g & 1) * 8u;
                const int rbase = tid_g >> 4;
                uint4 cc[4] = {c0, c1, c2, c3};
                #pragma unroll
                for (int j = 0; j < 4; j++) {
                    const int rj = rbase + 8 * j;
                    const float4 f = *(float4*)&cc[j];
                    const uint32_t addr = sA_g + (uint32_t)rj * 256u
                                        + (colu ^ (((uint32_t)(rj & 7)) << 4)) + sub;
                    sts64(addr, pack_h2(f.x, f.y), pack_h2(f.z, f.w));
                }
            }
            if (write_event && tid_g < 96) {
                int ei = mb * 96 + tid_g;
                out[(size_t)3 * NN * NF + ei] = (float)(ei & (NE - 1));
            }
        }
        BARG();   // sA_g ready (fast path)

        // ---- repair path (group-uniform; never taken for arange pidx) ----
        if (lds32(flagA) != 0u) {
            const float4* xsrc = (const float4*)(x + (size_t)pi_cur * NF) + gq2 * 4;
            float4 h0 = xsrc[0], h1 = xsrc[1], h2 = xsrc[2], h3 = xsrc[3];
            const uint32_t rb  = sA_g + (uint32_t)gr2 * 256u;
            const uint32_t msk = ((uint32_t)(gr2 & 7)) << 4;
            sts128(rb + (((uint32_t)gq2 * 32u) ^ msk),
                   pack_h2(h0.x, h0.y), pack_h2(h0.z, h0.w),
                   pack_h2(h1.x, h1.y), pack_h2(h1.z, h1.w));
            sts128(rb + (((uint32_t)gq2 * 32u + 16u) ^ msk),
                   pack_h2(h2.x, h2.y), pack_h2(h2.z, h2.w),
                   pack_h2(h3.x, h3.y), pack_h2(h3.z, h3.w));
            if (tid_g == 0) sts32(flagA, 0u);
            BARG();
        }

        // prefetch next tile's pidx
        {
            int mn = mb + gstep;
            if (mn < NGT) pi_cur = pidx[mn * 32 + gr2];
        }

        // ---- GEMM1: C1(32x256) = A(32x128) @ W1 ----
        float acc1[2][8][4];
        #pragma unroll
        for (int mf=0; mf<2; mf++)
            #pragma unroll
            for (int nt=0; nt<8; nt++)
                #pragma unroll
                for (int i=0;i<4;i++) acc1[mf][nt][i]=0.f;

        #pragma unroll
        for (int kk = 0; kk < 8; kk++) {
            const uint32_t ksw  = (((uint32_t)(kk*32)) + ahi) ^ amask;
            const uint32_t koff = (((uint32_t)(kk*32)) + bq)  ^ bmsk;
            uint32_t A[2][4];
            #pragma unroll
            for (int mf = 0; mf < 2; mf++)
                ldmx4(A[mf][0],A[mf][1],A[mf][2],A[mf][3], a1Base[mf] + ksw);
            #pragma unroll
            for (int j = 0; j < 4; j++) {
                uint32_t b0,b1,b2,b3;
                ldmx4(b0,b1,b2,b3, b1Ldsm + (uint32_t)j*4096u + koff);
                #pragma unroll
                for (int mf = 0; mf < 2; mf++) {
                    mma16(acc1[mf][2*j],   A[mf][0],A[mf][1],A[mf][2],A[mf][3], b0, b1);
                    mma16(acc1[mf][2*j+1], A[mf][0],A[mf][1],A[mf][2],A[mf][3], b2, b3);
                }
            }
        }

        // ---- Epilogue 1: packed f16 bias+relu -> sH_g, keep own slice in regs ----
        uint32_t hA[2][8], hB[2][8];
        #pragma unroll
        for (int mf=0; mf<2; mf++){
            const uint32_t rb0 = sH_g + (uint32_t)(16*mf + grp) * 512u;
            const uint32_t rb1 = rb0 + 8u * 512u;
            #pragma unroll
            for (int nt=0; nt<8; nt++){
                uint32_t p01 = relu_bias_h2(acc1[mf][nt][0], acc1[mf][nt][1], bh2[nt]);
                uint32_t p23 = relu_bias_h2(acc1[mf][nt][2], acc1[mf][nt][3], bh2[nt]);
                const uint32_t csw = (((uint32_t)(128*wn + nt*16)) ^ (((uint32_t)grp) << 4)) + (uint32_t)(4*tig);
                sts32(rb0 + csw, p01);
                sts32(rb1 + csw, p23);
                hA[mf][nt] = p01; hB[mf][nt] = p23;
            }
        }
        BARG();   // sH_g ready; all warps past GEMM1 (sA_g reusable next iter)

        // ---- GEMM2: C2(32x128) = h(32x256) @ W2; own k-slice from registers ----
        float acc2[2][4][4];
        #pragma unroll
        for (int mf=0; mf<2; mf++)
            #pragma unroll
            for (int nt=0; nt<4; nt++)
                #pragma unroll
                for (int i=0;i<4;i++) acc2[mf][nt][i]=0.f;

        #pragma unroll
        for (int s = 0; s < 16; s++) {
            uint32_t A[2][4];
            if ((s >> 2) == wn) {
                const int kkl = s & 3;
                #pragma unroll
                for (int mf = 0; mf < 2; mf++) {
                    A[mf][0] = hA[mf][2*kkl];   A[mf][1] = hB[mf][2*kkl];
                    A[mf][2] = hA[mf][2*kkl+1]; A[mf][3] = hB[mf][2*kkl+1];
                }
            } else {
                const uint32_t ksw = (((uint32_t)(s*32)) + ahi) ^ amask;
                #pragma unroll
                for (int mf = 0; mf < 2; mf++)
                    ldmx4(A[mf][0],A[mf][1],A[mf][2],A[mf][3], a2Base[mf] + ksw);
            }
            const uint32_t koff = (((uint32_t)(s*32)) + bq) ^ bmsk;
            #pragma unroll
            for (int j = 0; j < 2; j++) {
                uint32_t b0,b1,b2,b3;
                ldmx4(b0,b1,b2,b3, b2Ldsm + (uint32_t)j*8192u + koff);
                #pragma unroll
                for (int mf = 0; mf < 2; mf++) {
                    mma16(acc2[mf][2*j],   A[mf][0],A[mf][1],A[mf][2],A[mf][3], b0, b1);
                    mma16(acc2[mf][2*j+1], A[mf][0],A[mf][1],A[mf][2],A[mf][3], b2, b3);
                }
            }
        }

        // ---- Epilogue 2: bias + branch-permuted scatter ----
        const int p  = mb >> 8;
        const int e0 = (mb << 5) & (NE - 1);
        #pragma unroll
        for (int mf=0; mf<2; mf++){
            const int r0 = 16*mf + grp;
            #pragma unroll
            for (int nt=0; nt<4; nt++){
                const int c0 = nb2 + nt*8 + 2*tig;
                const int br = c0 >> 6, fc = c0 & 63;
                const size_t rowbase = (size_t)NN + (size_t)(2*p + br) * NE + (size_t)e0;
                float bz0 = sb2[c0], bz1 = sb2[c0+1];
                float2 v0 = { acc2[mf][nt][0] + bz0, acc2[mf][nt][1] + bz1 };
                float2 v1 = { acc2[mf][nt][2] + bz0, acc2[mf][nt][3] + bz1 };
                *(float2*)(out + (rowbase + r0)     * NF + fc) = v0;
                *(float2*)(out + (rowbase + r0 + 8) * NF + fc) = v1;
            }
        }
    }
    #undef BARG
}

extern "C" void kernel_launch(void* const* d_in, const int* in_sizes, int n_in,
                              void* d_out, int out_size)
{
    const float* x   = (const float*)d_in[0];
    const float* gf  = (const float*)d_in[1];
    const float* W1  = (const float*)d_in[2];
    const float* b1  = (const float*)d_in[3];
    const float* W2  = (const float*)d_in[4];
    const float* b2  = (const float*)d_in[5];
    const int*  pidx = (const int*)d_in[6];
    float* out = (float*)d_out;

    int write_event = (out_size >= (3 * NN * NF + 3 * NN)) ? 1 : 0;

    int dev = 0, nsm = 148;
    cudaGetDevice(&dev);
    cudaDeviceGetAttribute(&nsm, cudaDevAttrMultiProcessorCount, dev);
    if (nsm <= 0 || nsm > 8192) nsm = 148;

    cudaFuncSetAttribute(fused_h16m, cudaFuncAttributeMaxDynamicSharedMemorySize, SMEM_REQ);
    fused_h16m<<<nsm, NTHREADS, SMEM_REQ>>>(x, gf, W1, b1, W2, b2, pidx, out, write_event);
}